// round 16
// baseline (speedup 1.0000x reference)
#include <cuda_runtime.h>
#include <cuda_fp16.h>

#define NB  64
#define CCH 3
#define HH  256
#define WW  256
#define DD  512

struct BParam { float m00, m01, m02, m10, m11, m12, w1, lev; int l0; };

__device__ BParam g_bp[NB];

// HWC4 fp16 texels: uint2 = {half2(r,g), half2(b,0)} = 8 bytes/px.
__device__ __align__(16) uint2 g_img4[NB * 256 * 256];
__device__ __align__(16) uint2 g_pyr14[NB * 128 * 128];
__device__ __align__(16) uint2 g_pyr24[NB * 64 * 64];
__device__ __align__(16) uint2 g_pyr34[NB * 32 * 32];

__device__ __forceinline__ float3 h4_to_f3(uint2 v) {
    __half2 rg = *reinterpret_cast<__half2*>(&v.x);
    __half2 bz = *reinterpret_cast<__half2*>(&v.y);
    float2 f0 = __half22float2(rg);
    float2 f1 = __half22float2(bz);
    return make_float3(f0.x, f0.y, f1.x);
}
__device__ __forceinline__ uint2 f3_to_h4(float r, float g, float b) {
    __half2 rg = __floats2half2_rn(r, g);
    __half2 bz = __floats2half2_rn(b, 0.f);
    uint2 o;
    o.x = *reinterpret_cast<unsigned*>(&rg);
    o.y = *reinterpret_cast<unsigned*>(&bz);
    return o;
}
__device__ __forceinline__ int refl(int v, int S) {
    v = v < 0 ? -v : v;
    return v >= S ? 2 * S - 2 - v : v;
}

// ---------------------------------------------------------------------------
// Kernel 1 (fused): blocks [0, NB*256) do CHW->HWC4-fp16 transpose + down0
// for a 32x8 img tile; blocks [NB*256, NB*256+NB) are one params block per
// batch (linear head + affine params + g_bp). pyr1 is computed
// unconditionally (g_bp isn't available intra-launch).
// ---------------------------------------------------------------------------
__global__ void fused0_kernel(const float* __restrict__ img,
                              const float* __restrict__ feat,
                              const float* __restrict__ lw,
                              const float* __restrict__ lb,
                              float* __restrict__ out_mat,
                              float* __restrict__ out_aff) {
    if (blockIdx.x >= NB * 256) {
        // ---- params role ----
        int n = blockIdx.x - NB * 256;
        if (threadIdx.x >= 128) return;
        int warp = threadIdx.x >> 5, lane = threadIdx.x & 31;
        const float* f  = feat + n * DD;
        const float* wr = lw + warp * DD;
        float s = 0.f;
        #pragma unroll 4
        for (int k = lane; k < DD; k += 32) s += f[k] * wr[k];
        #pragma unroll
        for (int o = 16; o; o >>= 1) s += __shfl_xor_sync(0xffffffffu, s, o);
        __shared__ float p[4];
        if (lane == 0) p[warp] = s + lb[warp];
        __syncthreads();
        if (threadIdx.x == 0) {
            float rot = tanhf(p[0]) * 3.14159265358979323846f;
            float sc  = expf(p[1]);
            float sx  = p[2], sy = p[3];
            float cs = cosf(rot), sn = sinf(rot);
            float m00 = sc * cs, m01 = -sc * sn, m10 = sc * sn, m11 = sc * cs;
            float* mo = out_mat + n * 6;
            mo[0] = m00; mo[1] = m01; mo[2] = sx;
            mo[3] = m10; mo[4] = m11; mo[5] = sy;
            float* ao = out_aff + n * 4;
            ao[0] = rot; ao[1] = sc; ao[2] = sx; ao[3] = sy;
            // Affine warp: jacobian constant per batch; H==W -> both column
            // norms equal exactly sc. levels = clip(log2(max(sc,1)), 0, 2.5)
            float level = log2f(fmaxf(sc, 1.f));
            level = fminf(fmaxf(level, 0.f), 2.5f);
            int l0 = (int)level;
            if (l0 > 2) l0 = 2;
            BParam bp;
            bp.m00 = m00; bp.m01 = m01; bp.m02 = sx;
            bp.m10 = m10; bp.m11 = m11; bp.m12 = sy;
            bp.w1 = level - (float)l0; bp.l0 = l0; bp.lev = level;
            g_bp[n] = bp;
        }
        return;
    }

    // ---- transpose + down0 role ----
    int bx = blockIdx.x & 7;
    int by = (blockIdx.x >> 3) & 31;
    int n  = blockIdx.x >> 8;
    int tx = threadIdx.x & 31, ty = threadIdx.x >> 5;
    int R0 = by * 8, C0 = bx * 32;

    __shared__ uint2 st[10][35];        // rows -1..8, cols -1..33 (34 used)

    const float* p = img + (size_t)n * 3 * 65536 + (R0 + ty) * 256 + C0 + tx;
    float r = __ldg(p), g = __ldg(p + 65536), b = __ldg(p + 131072);
    uint2 t = f3_to_h4(r, g, b);
    g_img4[(size_t)n * 65536 + (R0 + ty) * 256 + C0 + tx] = t;

    st[ty + 1][tx + 1] = t;

    // Halo: rows -1 & 8 (34 cols each), cols -1 & 32 for rows 0..7. 84 texels.
    int i = threadIdx.x;
    if (i < 84) {
        int hr, hc;
        if (i < 34)       { hr = -1; hc = i - 1; }
        else if (i < 68)  { hr = 8;  hc = i - 35; }
        else              { hr = (i - 68) >> 1; hc = ((i - 68) & 1) ? 32 : -1; }
        int gr = refl(R0 + hr, 256);
        int gc = refl(C0 + hc, 256);
        const float* q = img + (size_t)n * 3 * 65536 + gr * 256 + gc;
        st[hr + 1][hc + 1] = f3_to_h4(__ldg(q), __ldg(q + 65536), __ldg(q + 131072));
    }
    __syncthreads();

    // pyr1 tile 16 wide x 4 tall at (4*by, 16*bx). Threads 0..63.
    if (threadIdx.x < 64) {
        int ow = threadIdx.x & 15, oh = threadIdx.x >> 4;
        const float kk[4] = {0.125f, 0.375f, 0.375f, 0.125f};
        float ax = 0.f, ay = 0.f, az = 0.f;
        #pragma unroll
        for (int ii = 0; ii < 4; ii++) {
            int sr = 2 * oh + ii;
            #pragma unroll
            for (int jj = 0; jj < 4; jj++) {
                int sc = 2 * ow + jj;
                float w = kk[ii] * kk[jj];
                float3 v = h4_to_f3(st[sr][sc]);
                ax += w * v.x; ay += w * v.y; az += w * v.z;
            }
        }
        g_pyr14[(size_t)n * 16384 + (4 * by + oh) * 128 + 16 * bx + ow] =
            f3_to_h4(ax, ay, az);
    }
}

// ---------------------------------------------------------------------------
// Downsample tap (global source): reflect pad (1,2), separable [1,3,3,1]/8.
// ---------------------------------------------------------------------------
template <int Si>
__device__ __forceinline__ uint2 down_tap(const uint2* __restrict__ src,
                                          int oh, int ow) {
    const float kk[4] = {0.125f, 0.375f, 0.375f, 0.125f};
    int rr[4], cc[4];
    #pragma unroll
    for (int i = 0; i < 4; i++) {
        rr[i] = refl(2 * oh - 1 + i, Si) * Si;
        cc[i] = refl(2 * ow - 1 + i, Si);
    }
    float ax = 0.f, ay = 0.f, az = 0.f;
    #pragma unroll
    for (int i = 0; i < 4; i++) {
        #pragma unroll
        for (int j = 0; j < 4; j++) {
            float w = kk[i] * kk[j];
            float3 v = h4_to_f3(__ldg(src + rr[i] + cc[j]));
            ax += w * v.x; ay += w * v.y; az += w * v.z;
        }
    }
    return f3_to_h4(ax, ay, az);
}

// ---------------------------------------------------------------------------
// Kernel 2: down1 + down2 in ONE launch. blockIdx.y = batch.
// ---------------------------------------------------------------------------
__global__ void down12_kernel() {
    int n = blockIdx.y;
    float lev = g_bp[n].lev;
    int j = blockIdx.x * blockDim.x + threadIdx.x;    // 0..5119

    if (j < 4096) {
        if (lev <= 1.f) return;
        g_pyr24[(size_t)n * 4096 + j] =
            down_tap<128>(g_pyr14 + (size_t)n * 16384, j >> 6, j & 63);
    } else {
        if (lev <= 2.f) return;
        int j2 = j - 4096;
        int oh = j2 >> 5, ow = j2 & 31;
        const uint2* p1 = g_pyr14 + (size_t)n * 16384;
        const float kk[4] = {0.125f, 0.375f, 0.375f, 0.125f};
        float ax = 0.f, ay = 0.f, az = 0.f;
        #pragma unroll
        for (int ii = 0; ii < 4; ii++) {
            int r2 = refl(2 * oh - 1 + ii, 64);
            #pragma unroll
            for (int jj = 0; jj < 4; jj++) {
                int c2 = refl(2 * ow - 1 + jj, 64);
                float w = kk[ii] * kk[jj];
                float3 v = h4_to_f3(down_tap<128>(p1, r2, c2));
                ax += w * v.x; ay += w * v.y; az += w * v.z;
            }
        }
        g_pyr34[(size_t)n * 1024 + j2] = f3_to_h4(ax, ay, az);
    }
}

// ---------------------------------------------------------------------------
// Bilinear sample in texel space. CLAMP=false = interior fast path.
// ---------------------------------------------------------------------------
template <bool CLAMP>
__device__ __forceinline__ void sample_t(const uint2* __restrict__ base, int S,
                                         float xs, float ys, float wgt,
                                         float* acc) {
    float xf = floorf(xs), yf = floorf(ys);
    float tx = xs - xf, ty = ys - yf;
    int x0 = (int)xf, y0 = (int)yf;
    int x1 = x0 + 1, y1 = y0 + 1;
    if (CLAMP) {
        x0 = min(max(x0, 0), S - 1);
        x1 = min(max(x1, 0), S - 1);
        y0 = min(max(y0, 0), S - 1);
        y1 = min(max(y1, 0), S - 1);
    }
    float w00 = (1.f - tx) * (1.f - ty) * wgt;
    float w01 = tx * (1.f - ty) * wgt;
    float w10 = (1.f - tx) * ty * wgt;
    float w11 = tx * ty * wgt;
    const uint2* r0 = base + y0 * S;
    const uint2* r1 = base + y1 * S;
    float3 v00 = h4_to_f3(__ldg(r0 + x0));
    float3 v01 = h4_to_f3(__ldg(r0 + x1));
    float3 v10 = h4_to_f3(__ldg(r1 + x0));
    float3 v11 = h4_to_f3(__ldg(r1 + x1));
    acc[0] += v00.x*w00 + v01.x*w01 + v10.x*w10 + v11.x*w11;
    acc[1] += v00.y*w00 + v01.y*w01 + v10.y*w10 + v11.y*w11;
    acc[2] += v00.z*w00 + v01.z*w01 + v10.z*w10 + v11.z*w11;
}

// Per-level texel-space mapping + interior test for a 16x16 px block tile.
struct LvlMap { float aw, ah, ac, bw, bh, bc; bool interior; };
__device__ __forceinline__ LvlMap make_lvl(const BParam& bp, int S,
                                           float cw0, float cw1,
                                           float ch0, float ch1) {
    float hs = 0.5f * (float)S;
    LvlMap m;
    m.aw = bp.m00 * hs; m.ah = bp.m01 * hs; m.ac = (bp.m02 + 1.f) * hs - 0.5f;
    m.bw = bp.m10 * hs; m.bh = bp.m11 * hs; m.bc = (bp.m12 + 1.f) * hs - 0.5f;
    float xmin = 1e30f, xmax = -1e30f, ymin = 1e30f, ymax = -1e30f;
    float cs[2] = {cw0, cw1}, hh[2] = {ch0, ch1};
    #pragma unroll
    for (int i = 0; i < 2; i++)
        #pragma unroll
        for (int j = 0; j < 2; j++) {
            float x = m.aw * cs[i] + m.ah * hh[j] + m.ac;
            float y = m.bw * cs[i] + m.bh * hh[j] + m.bc;
            xmin = fminf(xmin, x); xmax = fmaxf(xmax, x);
            ymin = fminf(ymin, y); ymax = fmaxf(ymax, y);
        }
    m.interior = (xmin >= 1.f) && (ymin >= 1.f) &&
                 (xmax <= (float)(S - 2)) && (ymax <= (float)(S - 2));
    return m;
}

// ---------------------------------------------------------------------------
// Kernel 3: grid gen + mipmap warp (thread = 2 px in w, warp tile 16w x 4h,
// texel-space affine + interior clamp-free fast path).
// ---------------------------------------------------------------------------
__global__ void warp_kernel(float* __restrict__ out,
                            float* __restrict__ grid_out) {
    int n  = blockIdx.z;
    int tx = threadIdx.x, ty = threadIdx.y;
    int W0 = blockIdx.x * 16, H0 = blockIdx.y * 16;
    int w0 = W0 + tx * 2;
    int h  = H0 + ty;

    BParam bp = g_bp[n];

    float wc  = ((float)w0 + 0.5f) * (2.f / (float)WW) - 1.f;
    float hc  = ((float)h + 0.5f) * (2.f / (float)HH) - 1.f;
    float dwc = 2.f / (float)WW;
    float gx0 = bp.m00 * wc + bp.m01 * hc + bp.m02;
    float gy0 = bp.m10 * wc + bp.m11 * hc + bp.m12;
    float gx1 = gx0 + bp.m00 * dwc;
    float gy1 = gy0 + bp.m10 * dwc;

    {   // grid store: 2 px = float4, 16B aligned, evict-first
        float* gp = grid_out + ((size_t)n * 65536 + (size_t)h * 256 + w0) * 2;
        __stcs(reinterpret_cast<float4*>(gp), make_float4(gx0, gy0, gx1, gy1));
    }

    int l0 = bp.l0;
    float w1 = bp.w1;
    float wgt0 = 1.f - w1;

    const uint2* b0; int s0;
    if (l0 == 0)      { b0 = g_img4  + (size_t)n * 65536; s0 = 256; }
    else if (l0 == 1) { b0 = g_pyr14 + (size_t)n * 16384; s0 = 128; }
    else              { b0 = g_pyr24 + (size_t)n * 4096;  s0 = 64;  }

    const uint2* b1 = nullptr; int s1 = 0;
    if (w1 > 0.f) {
        if (l0 == 0)      { b1 = g_pyr14 + (size_t)n * 16384; s1 = 128; }
        else if (l0 == 1) { b1 = g_pyr24 + (size_t)n * 4096;  s1 = 64;  }
        else              { b1 = g_pyr34 + (size_t)n * 1024;  s1 = 32;  }
    }

    // Block-tile corner coords (normalized), for interior tests.
    float cw0 = ((float)W0 + 0.5f)  * (2.f / 256.f) - 1.f;
    float cw1 = ((float)W0 + 15.5f) * (2.f / 256.f) - 1.f;
    float ch0 = ((float)H0 + 0.5f)  * (2.f / 256.f) - 1.f;
    float ch1 = ((float)H0 + 15.5f) * (2.f / 256.f) - 1.f;

    float a0[3] = {0.f, 0.f, 0.f};
    float a1[3] = {0.f, 0.f, 0.f};

    {   // primary level
        LvlMap m = make_lvl(bp, s0, cw0, cw1, ch0, ch1);
        float xs0 = m.aw * wc + m.ah * hc + m.ac;
        float ys0 = m.bw * wc + m.bh * hc + m.bc;
        float xs1 = xs0 + m.aw * dwc;
        float ys1 = ys0 + m.bw * dwc;
        if (m.interior) {
            sample_t<false>(b0, s0, xs0, ys0, wgt0, a0);
            sample_t<false>(b0, s0, xs1, ys1, wgt0, a1);
        } else {
            sample_t<true>(b0, s0, xs0, ys0, wgt0, a0);
            sample_t<true>(b0, s0, xs1, ys1, wgt0, a1);
        }
    }
    if (b1) {  // secondary level (batch-uniform)
        LvlMap m = make_lvl(bp, s1, cw0, cw1, ch0, ch1);
        float xs0 = m.aw * wc + m.ah * hc + m.ac;
        float ys0 = m.bw * wc + m.bh * hc + m.bc;
        float xs1 = xs0 + m.aw * dwc;
        float ys1 = ys0 + m.bw * dwc;
        if (m.interior) {
            sample_t<false>(b1, s1, xs0, ys0, w1, a0);
            sample_t<false>(b1, s1, xs1, ys1, w1, a1);
        } else {
            sample_t<true>(b1, s1, xs0, ys0, w1, a0);
            sample_t<true>(b1, s1, xs1, ys1, w1, a1);
        }
    }

    // out stores: 3 channels x float2 (2 px along w), 8B aligned.
    float* o = out + (size_t)n * 3 * 65536 + (size_t)h * 256 + w0;
    __stcs(reinterpret_cast<float2*>(o),          make_float2(a0[0], a1[0]));
    __stcs(reinterpret_cast<float2*>(o + 65536),  make_float2(a0[1], a1[1]));
    __stcs(reinterpret_cast<float2*>(o + 131072), make_float2(a0[2], a1[2]));
}

// ---------------------------------------------------------------------------
extern "C" void kernel_launch(void* const* d_in, const int* in_sizes, int n_in,
                              void* d_out, int out_size) {
    const float* img  = (const float*)d_in[0];
    const float* feat = (const float*)d_in[1];
    const float* lw   = (const float*)d_in[2];
    const float* lb   = (const float*)d_in[3];

    float* base   = (float*)d_out;
    float* out_p  = base;                                   // N*C*H*W
    float* grid_p = base + (size_t)NB * CCH * HH * WW;
    float* mat_p  = grid_p + (size_t)NB * HH * WW * 2;
    float* aff_p  = mat_p + NB * 6;

    fused0_kernel<<<NB * 256 + NB, 256>>>(img, feat, lw, lb, mat_p, aff_p);
    {
        dim3 g(20, NB);                                     // 5120 threads/batch
        down12_kernel<<<g, 256>>>();
    }

    dim3 blk(8, 16);
    dim3 grd(WW / 16, HH / 16, NB);
    warp_kernel<<<grd, blk>>>(out_p, grid_p);
}

// round 17
// speedup vs baseline: 1.1256x; 1.1256x over previous
#include <cuda_runtime.h>
#include <cuda_fp16.h>

#define NB  64
#define CCH 3
#define HH  256
#define WW  256
#define DD  512

struct BParam { float m00, m01, m02, m10, m11, m12, w1, lev; int l0; };

__device__ BParam g_bp[NB];

// HWC4 fp16 texels: uint2 = {half2(r,g), half2(b,0)} = 8 bytes/px.
__device__ __align__(16) uint2 g_img4[NB * 256 * 256];
__device__ __align__(16) uint2 g_pyr14[NB * 128 * 128];
__device__ __align__(16) uint2 g_pyr24[NB * 64 * 64];
__device__ __align__(16) uint2 g_pyr34[NB * 32 * 32];

__device__ __forceinline__ float3 h4_to_f3(uint2 v) {
    __half2 rg = *reinterpret_cast<__half2*>(&v.x);
    __half2 bz = *reinterpret_cast<__half2*>(&v.y);
    float2 f0 = __half22float2(rg);
    float2 f1 = __half22float2(bz);
    return make_float3(f0.x, f0.y, f1.x);
}
__device__ __forceinline__ uint2 f3_to_h4(float r, float g, float b) {
    __half2 rg = __floats2half2_rn(r, g);
    __half2 bz = __floats2half2_rn(b, 0.f);
    uint2 o;
    o.x = *reinterpret_cast<unsigned*>(&rg);
    o.y = *reinterpret_cast<unsigned*>(&bz);
    return o;
}
__device__ __forceinline__ int refl(int v, int S) {
    v = v < 0 ? -v : v;
    return v >= S ? 2 * S - 2 - v : v;
}

// ---------------------------------------------------------------------------
// Kernel 1: linear head + affine params. One block per batch, 4 warps.
// ---------------------------------------------------------------------------
__global__ void params_kernel(const float* __restrict__ feat,
                              const float* __restrict__ lw,
                              const float* __restrict__ lb,
                              float* __restrict__ out_mat,
                              float* __restrict__ out_aff) {
    int n = blockIdx.x;
    int warp = threadIdx.x >> 5, lane = threadIdx.x & 31;
    const float* f  = feat + n * DD;
    const float* wr = lw + warp * DD;
    float s = 0.f;
    #pragma unroll 4
    for (int k = lane; k < DD; k += 32) s += f[k] * wr[k];
    #pragma unroll
    for (int o = 16; o; o >>= 1) s += __shfl_xor_sync(0xffffffffu, s, o);
    __shared__ float p[4];
    if (lane == 0) p[warp] = s + lb[warp];
    __syncthreads();
    if (threadIdx.x == 0) {
        float rot = tanhf(p[0]) * 3.14159265358979323846f;
        float sc  = expf(p[1]);
        float sx  = p[2], sy = p[3];
        float cs = cosf(rot), sn = sinf(rot);
        float m00 = sc * cs, m01 = -sc * sn, m10 = sc * sn, m11 = sc * cs;
        float* mo = out_mat + n * 6;
        mo[0] = m00; mo[1] = m01; mo[2] = sx;
        mo[3] = m10; mo[4] = m11; mo[5] = sy;
        float* ao = out_aff + n * 4;
        ao[0] = rot; ao[1] = sc; ao[2] = sx; ao[3] = sy;
        // Affine warp: jacobian constant per batch; H==W -> both column norms
        // equal exactly sc. levels = clip(log2(max(sc,1)), 0, 2.5)
        float level = log2f(fmaxf(sc, 1.f));
        level = fminf(fmaxf(level, 0.f), 2.5f);
        int l0 = (int)level;
        if (l0 > 2) l0 = 2;
        BParam bp;
        bp.m00 = m00; bp.m01 = m01; bp.m02 = sx;
        bp.m10 = m10; bp.m11 = m11; bp.m12 = sy;
        bp.w1 = level - (float)l0; bp.l0 = l0; bp.lev = level;
        g_bp[n] = bp;
    }
}

// ---------------------------------------------------------------------------
// Kernel 2: fused CHW->HWC4-fp16 transpose + down0, wide tiles.
// Block = 64x16 img tile, 256 threads, 4 px/thread via float4 loads.
// pyr1 tile 32x8 computed from smem (164-texel reflected halo).
// ---------------------------------------------------------------------------
__global__ void hwc0_kernel(const float* __restrict__ img) {
    int bx = blockIdx.x & 3;            // 4 x-tiles of 64 px
    int by = (blockIdx.x >> 2) & 15;    // 16 y-tiles of 16 px
    int n  = blockIdx.x >> 6;
    int R0 = by * 16, C0 = bx * 64;

    // smem: local input rows -1..16 (18), cols -1..64 (66) + pad -> 67
    __shared__ uint2 st[18][67];

    int row  = threadIdx.x >> 4;            // 0..15
    int col4 = (threadIdx.x & 15) * 4;      // 0..60 step 4

    const float* p = img + (size_t)n * 3 * 65536 + (R0 + row) * 256 + C0 + col4;
    float4 r = *reinterpret_cast<const float4*>(p);
    float4 g = *reinterpret_cast<const float4*>(p + 65536);
    float4 b = *reinterpret_cast<const float4*>(p + 131072);
    uint2 o0 = f3_to_h4(r.x, g.x, b.x);
    uint2 o1 = f3_to_h4(r.y, g.y, b.y);
    uint2 o2 = f3_to_h4(r.z, g.z, b.z);
    uint2 o3 = f3_to_h4(r.w, g.w, b.w);
    {
        size_t idx = (size_t)n * 65536 + (R0 + row) * 256 + C0 + col4;
        uint4* dst = reinterpret_cast<uint4*>(g_img4 + idx);
        dst[0] = make_uint4(o0.x, o0.y, o1.x, o1.y);
        dst[1] = make_uint4(o2.x, o2.y, o3.x, o3.y);
    }

    if (g_bp[n].lev <= 0.f) return;     // pyramid unused (uniform per block)

    st[row + 1][col4 + 1] = o0;
    st[row + 1][col4 + 2] = o1;
    st[row + 1][col4 + 3] = o2;
    st[row + 1][col4 + 4] = o3;

    // Halo (164 texels): rows -1 & 16 (66 cols each incl corners),
    // cols -1 & 64 for rows 0..15 (32).
    int i = threadIdx.x;
    if (i < 164) {
        int hr, hc;
        if (i < 66)       { hr = -1; hc = i - 1; }
        else if (i < 132) { hr = 16; hc = i - 67; }
        else              { hr = (i - 132) >> 1; hc = ((i - 132) & 1) ? 64 : -1; }
        int gr = refl(R0 + hr, 256);
        int gc = refl(C0 + hc, 256);
        const float* q = img + (size_t)n * 3 * 65536 + gr * 256 + gc;
        st[hr + 1][hc + 1] = f3_to_h4(__ldg(q), __ldg(q + 65536), __ldg(q + 131072));
    }
    __syncthreads();

    // pyr1 tile 32 wide x 8 tall at (8*by, 32*bx). One output per thread.
    {
        int ow = threadIdx.x & 31, oh = threadIdx.x >> 5;
        const float kk[4] = {0.125f, 0.375f, 0.375f, 0.125f};
        float ax = 0.f, ay = 0.f, az = 0.f;
        #pragma unroll
        for (int ii = 0; ii < 4; ii++) {
            int sr = 2 * oh + ii;               // local tap row (+1 offset)
            #pragma unroll
            for (int jj = 0; jj < 4; jj++) {
                int sc = 2 * ow + jj;           // local tap col (+1 offset)
                float w = kk[ii] * kk[jj];
                float3 v = h4_to_f3(st[sr][sc]);
                ax += w * v.x; ay += w * v.y; az += w * v.z;
            }
        }
        g_pyr14[(size_t)n * 16384 + (8 * by + oh) * 128 + 32 * bx + ow] =
            f3_to_h4(ax, ay, az);
    }
}

// ---------------------------------------------------------------------------
// Downsample tap (global source): reflect pad (1,2), separable [1,3,3,1]/8.
// ---------------------------------------------------------------------------
template <int Si>
__device__ __forceinline__ uint2 down_tap(const uint2* __restrict__ src,
                                          int oh, int ow) {
    const float kk[4] = {0.125f, 0.375f, 0.375f, 0.125f};
    int rr[4], cc[4];
    #pragma unroll
    for (int i = 0; i < 4; i++) {
        rr[i] = refl(2 * oh - 1 + i, Si) * Si;
        cc[i] = refl(2 * ow - 1 + i, Si);
    }
    float ax = 0.f, ay = 0.f, az = 0.f;
    #pragma unroll
    for (int i = 0; i < 4; i++) {
        #pragma unroll
        for (int j = 0; j < 4; j++) {
            float w = kk[i] * kk[j];
            float3 v = h4_to_f3(__ldg(src + rr[i] + cc[j]));
            ax += w * v.x; ay += w * v.y; az += w * v.z;
        }
    }
    return f3_to_h4(ax, ay, az);
}

// ---------------------------------------------------------------------------
// Kernel 3: down1 + down2 in ONE launch. blockIdx.y = batch.
// ---------------------------------------------------------------------------
__global__ void down12_kernel() {
    int n = blockIdx.y;
    float lev = g_bp[n].lev;
    int j = blockIdx.x * blockDim.x + threadIdx.x;    // 0..5119

    if (j < 4096) {
        if (lev <= 1.f) return;
        g_pyr24[(size_t)n * 4096 + j] =
            down_tap<128>(g_pyr14 + (size_t)n * 16384, j >> 6, j & 63);
    } else {
        if (lev <= 2.f) return;
        int j2 = j - 4096;
        int oh = j2 >> 5, ow = j2 & 31;
        const uint2* p1 = g_pyr14 + (size_t)n * 16384;
        const float kk[4] = {0.125f, 0.375f, 0.375f, 0.125f};
        float ax = 0.f, ay = 0.f, az = 0.f;
        #pragma unroll
        for (int ii = 0; ii < 4; ii++) {
            int r2 = refl(2 * oh - 1 + ii, 64);
            #pragma unroll
            for (int jj = 0; jj < 4; jj++) {
                int c2 = refl(2 * ow - 1 + jj, 64);
                float w = kk[ii] * kk[jj];
                float3 v = h4_to_f3(down_tap<128>(p1, r2, c2));
                ax += w * v.x; ay += w * v.y; az += w * v.z;
            }
        }
        g_pyr34[(size_t)n * 1024 + j2] = f3_to_h4(ax, ay, az);
    }
}

// ---------------------------------------------------------------------------
// Bilinear sample (border clamp) from an HWC4-fp16 plane. One uint2 per tap.
// ---------------------------------------------------------------------------
__device__ __forceinline__ void sample4(const uint2* __restrict__ base, int S,
                                        float gx, float gy, float wgt,
                                        float* acc) {
    float x = fmaf(gx + 1.f, 0.5f * (float)S, -0.5f);
    float y = fmaf(gy + 1.f, 0.5f * (float)S, -0.5f);
    float xf = floorf(x), yf = floorf(y);
    float tx = x - xf, ty = y - yf;
    int x0 = (int)xf, y0 = (int)yf;
    int x0c = min(max(x0, 0), S - 1);
    int x1c = min(max(x0 + 1, 0), S - 1);
    int y0c = min(max(y0, 0), S - 1);
    int y1c = min(max(y0 + 1, 0), S - 1);
    float w00 = (1.f - tx) * (1.f - ty) * wgt;
    float w01 = tx * (1.f - ty) * wgt;
    float w10 = (1.f - tx) * ty * wgt;
    float w11 = tx * ty * wgt;
    const uint2* r0 = base + y0c * S;
    const uint2* r1 = base + y1c * S;
    float3 v00 = h4_to_f3(__ldg(r0 + x0c));
    float3 v01 = h4_to_f3(__ldg(r0 + x1c));
    float3 v10 = h4_to_f3(__ldg(r1 + x0c));
    float3 v11 = h4_to_f3(__ldg(r1 + x1c));
    acc[0] += v00.x*w00 + v01.x*w01 + v10.x*w10 + v11.x*w11;
    acc[1] += v00.y*w00 + v01.y*w01 + v10.y*w10 + v11.y*w11;
    acc[2] += v00.z*w00 + v01.z*w01 + v10.z*w10 + v11.z*w11;
}

// ---------------------------------------------------------------------------
// Kernel 4: grid gen + mipmap warp. Thread = 2 adjacent px in w; warp tile
// 16w x 4h (champion R11 configuration).
// ---------------------------------------------------------------------------
__global__ void warp_kernel(float* __restrict__ out,
                            float* __restrict__ grid_out) {
    int n  = blockIdx.z;
    int w0 = (blockIdx.x * 8 + threadIdx.x) * 2;
    int h  = blockIdx.y * 16 + threadIdx.y;

    BParam bp = g_bp[n];

    float wc  = ((float)w0 + 0.5f) * (2.f / (float)WW) - 1.f;
    float hc  = ((float)h + 0.5f) * (2.f / (float)HH) - 1.f;
    float dgx = bp.m00 * (2.f / (float)WW);          // per +1 in w
    float dgy = bp.m10 * (2.f / (float)WW);
    float gx0 = bp.m00 * wc + bp.m01 * hc + bp.m02;
    float gy0 = bp.m10 * wc + bp.m11 * hc + bp.m12;
    float gx1 = gx0 + dgx;
    float gy1 = gy0 + dgy;

    {   // grid store: 2 px = float4, 16B aligned (w0 even), evict-first
        float* gp = grid_out + ((size_t)n * 65536 + (size_t)h * 256 + w0) * 2;
        __stcs(reinterpret_cast<float4*>(gp), make_float4(gx0, gy0, gx1, gy1));
    }

    int l0 = bp.l0;
    float w1 = bp.w1;
    float wgt0 = 1.f - w1;

    const uint2* b0; int s0;
    if (l0 == 0)      { b0 = g_img4  + (size_t)n * 65536; s0 = 256; }
    else if (l0 == 1) { b0 = g_pyr14 + (size_t)n * 16384; s0 = 128; }
    else              { b0 = g_pyr24 + (size_t)n * 4096;  s0 = 64;  }

    const uint2* b1 = nullptr; int s1 = 0;
    if (w1 > 0.f) {
        if (l0 == 0)      { b1 = g_pyr14 + (size_t)n * 16384; s1 = 128; }
        else if (l0 == 1) { b1 = g_pyr24 + (size_t)n * 4096;  s1 = 64;  }
        else              { b1 = g_pyr34 + (size_t)n * 1024;  s1 = 32;  }
    }

    float a0[3] = {0.f, 0.f, 0.f};
    float a1[3] = {0.f, 0.f, 0.f};
    sample4(b0, s0, gx0, gy0, wgt0, a0);
    sample4(b0, s0, gx1, gy1, wgt0, a1);
    if (b1) {
        sample4(b1, s1, gx0, gy0, w1, a0);
        sample4(b1, s1, gx1, gy1, w1, a1);
    }

    // out stores: 3 channels x float2 (2 px along w), 8B aligned.
    float* o = out + (size_t)n * 3 * 65536 + (size_t)h * 256 + w0;
    __stcs(reinterpret_cast<float2*>(o),          make_float2(a0[0], a1[0]));
    __stcs(reinterpret_cast<float2*>(o + 65536),  make_float2(a0[1], a1[1]));
    __stcs(reinterpret_cast<float2*>(o + 131072), make_float2(a0[2], a1[2]));
}

// ---------------------------------------------------------------------------
extern "C" void kernel_launch(void* const* d_in, const int* in_sizes, int n_in,
                              void* d_out, int out_size) {
    const float* img  = (const float*)d_in[0];
    const float* feat = (const float*)d_in[1];
    const float* lw   = (const float*)d_in[2];
    const float* lb   = (const float*)d_in[3];

    float* base   = (float*)d_out;
    float* out_p  = base;                                   // N*C*H*W
    float* grid_p = base + (size_t)NB * CCH * HH * WW;
    float* mat_p  = grid_p + (size_t)NB * HH * WW * 2;
    float* aff_p  = mat_p + NB * 6;

    params_kernel<<<NB, 128>>>(feat, lw, lb, mat_p, aff_p);
    hwc0_kernel<<<NB * 64, 256>>>(img);                     // transpose + down0
    {
        dim3 g(20, NB);                                     // 5120 threads/batch
        down12_kernel<<<g, 256>>>();
    }

    dim3 blk(8, 16);
    dim3 grd(WW / 16, HH / 16, NB);
    warp_kernel<<<grd, blk>>>(out_p, grid_p);
}